// round 1
// baseline (speedup 1.0000x reference)
#include <cuda_runtime.h>
#include <math.h>

#define EMBED 1024
#define HEADS 16
#define HDIM  64
#define BATCH 2
#define SEQ   2048
#define M_TOT (BATCH*SEQ)   // 4096

// Scratch (device globals: allocation-free per harness rules)
__device__ float g_q [BATCH*HEADS*SEQ*HDIM];
__device__ float g_k [BATCH*HEADS*SEQ*HDIM];
__device__ float g_v [BATCH*HEADS*SEQ*HDIM];
__device__ float g_ao[BATCH*SEQ*EMBED];

// ---------------------------------------------------------------------------
// C[m][n] = sum_k X[m][k] * W[n][k]   (y = x @ W.T), M=4096, N=K=1024
// 128x128 tile, BK=16, 256 threads, 8x8 micro-tile.
// SPLIT: scatter output into (B,H,S,D) head-split layout.
// ---------------------------------------------------------------------------
template<bool SPLIT>
__global__ __launch_bounds__(256) void gemm_xwt(const float* __restrict__ X,
                                                const float* __restrict__ W,
                                                float* __restrict__ out)
{
    __shared__ float As[16][132];   // [k][m], padded
    __shared__ float Bs[16][132];   // [k][n], padded

    const int tid = threadIdx.x;
    const int tx  = tid & 15, ty = tid >> 4;
    const int m0  = blockIdx.x * 128;
    const int n0  = blockIdx.y * 128;
    const int lm  = tid >> 2;          // 0..63
    const int lk  = (tid & 3) << 2;    // 0,4,8,12

    float acc[8][8];
    #pragma unroll
    for (int i = 0; i < 8; i++)
        #pragma unroll
        for (int j = 0; j < 8; j++) acc[i][j] = 0.f;

    for (int k0 = 0; k0 < EMBED; k0 += 16) {
        #pragma unroll
        for (int it = 0; it < 2; it++) {
            int r = lm + it * 64;
            float4 va = *(const float4*)(X + (size_t)(m0 + r) * EMBED + k0 + lk);
            As[lk+0][r] = va.x; As[lk+1][r] = va.y; As[lk+2][r] = va.z; As[lk+3][r] = va.w;
            float4 vb = *(const float4*)(W + (size_t)(n0 + r) * EMBED + k0 + lk);
            Bs[lk+0][r] = vb.x; Bs[lk+1][r] = vb.y; Bs[lk+2][r] = vb.z; Bs[lk+3][r] = vb.w;
        }
        __syncthreads();
        #pragma unroll
        for (int k = 0; k < 16; k++) {
            float a[8], b[8];
            *(float4*)&a[0] = *(const float4*)&As[k][ty*8];
            *(float4*)&a[4] = *(const float4*)&As[k][ty*8+4];
            *(float4*)&b[0] = *(const float4*)&Bs[k][tx*8];
            *(float4*)&b[4] = *(const float4*)&Bs[k][tx*8+4];
            #pragma unroll
            for (int i = 0; i < 8; i++)
                #pragma unroll
                for (int j = 0; j < 8; j++)
                    acc[i][j] = fmaf(a[i], b[j], acc[i][j]);
        }
        __syncthreads();
    }

    #pragma unroll
    for (int i = 0; i < 8; i++) {
        int m = m0 + ty*8 + i;
        #pragma unroll
        for (int j = 0; j < 8; j++) {
            int n = n0 + tx*8 + j;
            if (SPLIT) {
                int b = m >> 11, s = m & (SEQ-1);
                int h = n >> 6,  d = n & 63;
                out[(((size_t)(b*HEADS + h))*SEQ + s)*HDIM + d] = acc[i][j];
            } else {
                out[(size_t)m*EMBED + n] = acc[i][j];
            }
        }
    }
}

// ---------------------------------------------------------------------------
// Causal flash attention, fp32. One block = one (b,h) x 64-query tile.
// 256 threads (16x16), each owns a 4x4 sub-tile of scores and of output.
// Row groups: threads with equal ty (16 lanes in a half-warp) share a row.
// ---------------------------------------------------------------------------
#define PAD 68
__global__ __launch_bounds__(256) void flash_kernel(float* __restrict__ outAO)
{
    extern __shared__ float sm[];
    float* Qt = sm;              // [d][q]  64 x PAD
    float* Kt = sm + 64*PAD;     // [d][k]
    float* Vs = sm + 2*64*PAD;   // [k][d]
    float* Ps = sm + 3*64*PAD;   // [k][q]

    const int tid = threadIdx.x;
    const int tx  = tid & 15, ty = tid >> 4;
    const int bh  = blockIdx.y;
    const int b   = bh >> 4, h = bh & 15;
    const int qt  = blockIdx.x;
    const int q0  = qt * 64;

    const float* Qb = g_q + (size_t)bh * SEQ * HDIM;
    const float* Kb = g_k + (size_t)bh * SEQ * HDIM;
    const float* Vb = g_v + (size_t)bh * SEQ * HDIM;

    // Load Q tile transposed: Qt[d][q]
    {
        const int r0 = tid >> 4;           // 0..15
        const int d0 = (tid & 15) << 2;    // 0..60
        #pragma unroll
        for (int it = 0; it < 4; it++) {
            int q = r0 + it * 16;
            float4 v = *(const float4*)(Qb + (size_t)(q0 + q) * HDIM + d0);
            Qt[(d0+0)*PAD + q] = v.x;
            Qt[(d0+1)*PAD + q] = v.y;
            Qt[(d0+2)*PAD + q] = v.z;
            Qt[(d0+3)*PAD + q] = v.w;
        }
    }

    float m_i[4], l_i[4], o[4][4];
    #pragma unroll
    for (int i = 0; i < 4; i++) {
        m_i[i] = -INFINITY; l_i[i] = 0.f;
        #pragma unroll
        for (int j = 0; j < 4; j++) o[i][j] = 0.f;
    }

    const float scale = 0.03125f;  // 1/sqrt(1024)

    for (int kt = 0; kt <= qt; kt++) {
        const int k0 = kt * 64;
        __syncthreads();   // previous PV done reading Vs/Ps
        {
            const int r0 = tid >> 4;
            const int d0 = (tid & 15) << 2;
            #pragma unroll
            for (int it = 0; it < 4; it++) {
                int k = r0 + it * 16;
                float4 kv = *(const float4*)(Kb + (size_t)(k0 + k) * HDIM + d0);
                Kt[(d0+0)*PAD + k] = kv.x;
                Kt[(d0+1)*PAD + k] = kv.y;
                Kt[(d0+2)*PAD + k] = kv.z;
                Kt[(d0+3)*PAD + k] = kv.w;
                float4 vv = *(const float4*)(Vb + (size_t)(k0 + k) * HDIM + d0);
                *(float4*)(Vs + k*PAD + d0) = vv;
            }
        }
        __syncthreads();   // tiles ready

        // S = Q K^T (4x4 per thread)
        float s[4][4];
        #pragma unroll
        for (int i = 0; i < 4; i++)
            #pragma unroll
            for (int j = 0; j < 4; j++) s[i][j] = 0.f;

        #pragma unroll 8
        for (int d = 0; d < 64; d++) {
            float4 qa = *(const float4*)(Qt + d*PAD + ty*4);
            float4 ka = *(const float4*)(Kt + d*PAD + tx*4);
            float qv[4] = {qa.x, qa.y, qa.z, qa.w};
            float kv[4] = {ka.x, ka.y, ka.z, ka.w};
            #pragma unroll
            for (int i = 0; i < 4; i++)
                #pragma unroll
                for (int j = 0; j < 4; j++)
                    s[i][j] = fmaf(qv[i], kv[j], s[i][j]);
        }

        // scale + exact reference causal mask (-100000 above diagonal)
        #pragma unroll
        for (int i = 0; i < 4; i++) {
            int qg = q0 + ty*4 + i;
            #pragma unroll
            for (int j = 0; j < 4; j++) {
                int kg = k0 + tx*4 + j;
                s[i][j] = s[i][j] * scale + ((kg > qg) ? -100000.f : 0.f);
            }
        }

        // online softmax (row reduce over 16 lanes sharing ty)
        #pragma unroll
        for (int i = 0; i < 4; i++) {
            float mt = fmaxf(fmaxf(s[i][0], s[i][1]), fmaxf(s[i][2], s[i][3]));
            mt = fmaxf(mt, __shfl_xor_sync(0xffffffffu, mt, 8));
            mt = fmaxf(mt, __shfl_xor_sync(0xffffffffu, mt, 4));
            mt = fmaxf(mt, __shfl_xor_sync(0xffffffffu, mt, 2));
            mt = fmaxf(mt, __shfl_xor_sync(0xffffffffu, mt, 1));
            float mnew = fmaxf(m_i[i], mt);
            float corr = __expf(m_i[i] - mnew);
            float rs = 0.f;
            #pragma unroll
            for (int j = 0; j < 4; j++) {
                s[i][j] = __expf(s[i][j] - mnew);
                rs += s[i][j];
            }
            rs += __shfl_xor_sync(0xffffffffu, rs, 8);
            rs += __shfl_xor_sync(0xffffffffu, rs, 4);
            rs += __shfl_xor_sync(0xffffffffu, rs, 2);
            rs += __shfl_xor_sync(0xffffffffu, rs, 1);
            l_i[i] = l_i[i] * corr + rs;
            m_i[i] = mnew;
            #pragma unroll
            for (int j = 0; j < 4; j++) o[i][j] *= corr;
        }

        // stage P transposed: Ps[k][q]
        #pragma unroll
        for (int i = 0; i < 4; i++)
            #pragma unroll
            for (int j = 0; j < 4; j++)
                Ps[(tx*4 + j)*PAD + (ty*4 + i)] = s[i][j];
        __syncthreads();   // Ps ready

        // O += P V
        #pragma unroll 8
        for (int k = 0; k < 64; k++) {
            float4 pa = *(const float4*)(Ps + k*PAD + ty*4);
            float4 va = *(const float4*)(Vs + k*PAD + tx*4);
            float pv[4] = {pa.x, pa.y, pa.z, pa.w};
            float vv[4] = {va.x, va.y, va.z, va.w};
            #pragma unroll
            for (int i = 0; i < 4; i++)
                #pragma unroll
                for (int j = 0; j < 4; j++)
                    o[i][j] = fmaf(pv[i], vv[j], o[i][j]);
        }
    }

    // finalize: divide by l, write merged-head layout (B,S,E)
    #pragma unroll
    for (int i = 0; i < 4; i++) {
        float inv = 1.f / l_i[i];
        int qg = q0 + ty*4 + i;
        float4 r;
        r.x = o[i][0] * inv; r.y = o[i][1] * inv;
        r.z = o[i][2] * inv; r.w = o[i][3] * inv;
        *(float4*)(outAO + ((size_t)(b*SEQ + qg))*EMBED + h*HDIM + tx*4) = r;
    }
}

// ---------------------------------------------------------------------------
extern "C" void kernel_launch(void* const* d_in, const int* in_sizes, int n_in,
                              void* d_out, int out_size)
{
    const float* key   = (const float*)d_in[0];
    const float* query = (const float*)d_in[1];
    const float* value = (const float*)d_in[2];
    const float* Wk    = (const float*)d_in[3];
    const float* Wq    = (const float*)d_in[4];
    const float* Wv    = (const float*)d_in[5];
    const float* Wo    = (const float*)d_in[6];
    float* out = (float*)d_out;

    float *q_, *k_, *v_, *ao_;
    cudaGetSymbolAddress((void**)&q_,  g_q);
    cudaGetSymbolAddress((void**)&k_,  g_k);
    cudaGetSymbolAddress((void**)&v_,  g_v);
    cudaGetSymbolAddress((void**)&ao_, g_ao);

    dim3 gg(M_TOT/128, EMBED/128);   // (32, 8)
    gemm_xwt<true ><<<gg, 256>>>(query, Wq, q_);
    gemm_xwt<true ><<<gg, 256>>>(key,   Wk, k_);
    gemm_xwt<true ><<<gg, 256>>>(value, Wv, v_);

    int smem = 4 * 64 * PAD * (int)sizeof(float);   // 69,632 B
    cudaFuncSetAttribute(flash_kernel, cudaFuncAttributeMaxDynamicSharedMemorySize, smem);
    flash_kernel<<<dim3(SEQ/64, BATCH*HEADS), 256, smem>>>(ao_);

    gemm_xwt<false><<<gg, 256>>>(ao_, Wo, out);
}

// round 3
// speedup vs baseline: 1.6300x; 1.6300x over previous
#include <cuda_runtime.h>
#include <cuda_bf16.h>
#include <math.h>
#include <stdint.h>

#define EMBED 1024
#define HEADS 16
#define HDIM  64
#define BATCH 2
#define SEQ   2048
#define M_TOT (BATCH*SEQ)   // 4096

// ---------------- scratch (device globals; allocation-free) ----------------
__device__ float g_q [BATCH*HEADS*SEQ*HDIM];
__device__ float g_k [BATCH*HEADS*SEQ*HDIM];
__device__ float g_v [BATCH*HEADS*SEQ*HDIM];
__device__ float g_ao[BATCH*SEQ*EMBED];
__device__ __nv_bfloat16 g_xh[M_TOT*EMBED];
__device__ __nv_bfloat16 g_xl[M_TOT*EMBED];
__device__ __nv_bfloat16 g_wh[EMBED*EMBED];
__device__ __nv_bfloat16 g_wl[EMBED*EMBED];

// ---------------------------------------------------------------------------
// fp32 -> bf16 (hi, lo) split. 4 floats / thread.
// ---------------------------------------------------------------------------
__global__ __launch_bounds__(256) void cvt_hilo(const float* __restrict__ x,
                                                __nv_bfloat16* __restrict__ h,
                                                __nv_bfloat16* __restrict__ l)
{
    size_t i = (size_t)blockIdx.x * blockDim.x + threadIdx.x;
    float4 v = ((const float4*)x)[i];
    __nv_bfloat16 h0 = __float2bfloat16(v.x);
    __nv_bfloat16 h1 = __float2bfloat16(v.y);
    __nv_bfloat16 h2 = __float2bfloat16(v.z);
    __nv_bfloat16 h3 = __float2bfloat16(v.w);
    __nv_bfloat16 l0 = __float2bfloat16(v.x - __bfloat162float(h0));
    __nv_bfloat16 l1 = __float2bfloat16(v.y - __bfloat162float(h1));
    __nv_bfloat16 l2 = __float2bfloat16(v.z - __bfloat162float(h2));
    __nv_bfloat16 l3 = __float2bfloat16(v.w - __bfloat162float(h3));
    __nv_bfloat162* hp = (__nv_bfloat162*)h;
    __nv_bfloat162* lp = (__nv_bfloat162*)l;
    hp[2*i]   = __nv_bfloat162(h0, h1);
    hp[2*i+1] = __nv_bfloat162(h2, h3);
    lp[2*i]   = __nv_bfloat162(l0, l1);
    lp[2*i+1] = __nv_bfloat162(l2, l3);
}

// ---------------------------------------------------------------------------
// warp-MMA helpers (sm_80-class instructions; valid on plain sm_103 target)
// ---------------------------------------------------------------------------
__device__ __forceinline__ uint32_t s2u(const void* p) {
    uint32_t a;
    asm("{ .reg .u64 t; cvta.to.shared.u64 t, %1; cvt.u32.u64 %0, t; }" : "=r"(a) : "l"(p));
    return a;
}

__device__ __forceinline__ void ldmx4(uint32_t& r0, uint32_t& r1, uint32_t& r2, uint32_t& r3,
                                      uint32_t addr)
{
    asm volatile("ldmatrix.sync.aligned.m8n8.x4.shared.b16 {%0,%1,%2,%3}, [%4];"
                 : "=r"(r0), "=r"(r1), "=r"(r2), "=r"(r3) : "r"(addr));
}

__device__ __forceinline__ void mma16816(float* d, const uint32_t* a, const uint32_t* b)
{
    asm volatile("mma.sync.aligned.m16n8k16.row.col.f32.bf16.bf16.f32 "
                 "{%0,%1,%2,%3}, {%4,%5,%6,%7}, {%8,%9}, {%0,%1,%2,%3};"
                 : "+f"(d[0]), "+f"(d[1]), "+f"(d[2]), "+f"(d[3])
                 : "r"(a[0]), "r"(a[1]), "r"(a[2]), "r"(a[3]), "r"(b[0]), "r"(b[1]));
}

__device__ __forceinline__ void cpasync16(uint32_t saddr, const void* gaddr)
{
    asm volatile("cp.async.cg.shared.global [%0], [%1], 16;" :: "r"(saddr), "l"(gaddr));
}

__device__ __forceinline__ uint32_t swz(uint32_t off) { return off ^ ((off >> 3) & 0x70); }

// ---------------------------------------------------------------------------
// Tensor-core GEMM: C[m][n] = sum_k X[m][k]*W[n][k]  (fp32 via bf16 hi/lo, 3 passes)
// CTA tile 128x128, BK=64, 8 warps (2m x 4n), warptile 64x32.
// 2-stage cp.async pipeline. SPLIT: scatter into (B,H,S,D).
// ---------------------------------------------------------------------------
#define STG_BYTES 65536              // Ah 16K | Al 16K | Bh 16K | Bl 16K
#define GSMEM     (2 * STG_BYTES)    // 128 KB

template<bool SPLIT>
__global__ __launch_bounds__(256, 1) void gemm_tc(const __nv_bfloat16* __restrict__ xh,
                                                  const __nv_bfloat16* __restrict__ xl,
                                                  const __nv_bfloat16* __restrict__ wh,
                                                  const __nv_bfloat16* __restrict__ wl,
                                                  float* __restrict__ out)
{
    extern __shared__ char smg[];
    const uint32_t sb = s2u(smg);
    const int tid  = threadIdx.x;
    const int wid  = tid >> 5, lane = tid & 31;
    const int wm   = wid & 1;          // 0..1  (64-row slab)
    const int wn   = wid >> 1;         // 0..3  (32-col slab)
    const int m0   = blockIdx.x * 128;
    const int n0   = blockIdx.y * 128;

    // per-thread cp.async source/dest (4 rows apart per iter)
    const int ldr = tid >> 3;          // 0..31 (row)
    const int ldc = tid & 7;           // 0..7  (16B chunk)

    auto issue = [&](int c) {
        const int st = c & 1;
        const uint32_t sst = sb + st * STG_BYTES;
        const int kc0 = c * 64;
        const __nv_bfloat16* gAh = xh + (size_t)m0 * EMBED + kc0;
        const __nv_bfloat16* gAl = xl + (size_t)m0 * EMBED + kc0;
        const __nv_bfloat16* gBh = wh + (size_t)n0 * EMBED + kc0;
        const __nv_bfloat16* gBl = wl + (size_t)n0 * EMBED + kc0;
        #pragma unroll
        for (int it = 0; it < 4; it++) {
            const int r = ldr + it * 32;
            const uint32_t o = swz((uint32_t)(r * 128 + ldc * 16));
            const size_t g = (size_t)r * EMBED + ldc * 8;
            cpasync16(sst +          o, gAh + g);
            cpasync16(sst + 16384u + o, gAl + g);
            cpasync16(sst + 32768u + o, gBh + g);
            cpasync16(sst + 49152u + o, gBl + g);
        }
        asm volatile("cp.async.commit_group;" ::: "memory");
    };

    float d[4][4][4];
    #pragma unroll
    for (int mi = 0; mi < 4; mi++)
        #pragma unroll
        for (int ni = 0; ni < 4; ni++)
            #pragma unroll
            for (int r = 0; r < 4; r++) d[mi][ni][r] = 0.f;

    issue(0);

    const int NCHUNK = EMBED / 64;   // 16
    for (int c = 0; c < NCHUNK; c++) {
        if (c + 1 < NCHUNK) {
            issue(c + 1);
            asm volatile("cp.async.wait_group 1;" ::: "memory");
        } else {
            asm volatile("cp.async.wait_group 0;" ::: "memory");
        }
        __syncthreads();

        const uint32_t sst = sb + (c & 1) * STG_BYTES;
        const uint32_t aBase = sst;            // +16384 for lo
        const uint32_t bBase = sst + 32768u;   // +16384 for lo

        // ldmatrix thread->row/k mapping
        const int arow = lane & 15;
        const int akc  = (lane & 16) >> 1;     // 0 or 8
        const int brow = (lane & 7) | ((lane & 16) >> 1);
        const int bkc  = lane & 8;             // 0 or 8

        #pragma unroll
        for (int ks = 0; ks < 4; ks++) {
            uint32_t a[2][4][4];
            #pragma unroll
            for (int mi = 0; mi < 4; mi++) {
                const int row = wm * 64 + mi * 16 + arow;
                const uint32_t off = swz((uint32_t)(row * 128 + (ks * 16 + akc) * 2));
                ldmx4(a[0][mi][0], a[0][mi][1], a[0][mi][2], a[0][mi][3], aBase + off);
                ldmx4(a[1][mi][0], a[1][mi][1], a[1][mi][2], a[1][mi][3], aBase + 16384u + off);
            }
            uint32_t b[2][4][2];
            #pragma unroll
            for (int bi = 0; bi < 2; bi++) {
                const int row = wn * 32 + bi * 16 + brow;
                const uint32_t off = swz((uint32_t)(row * 128 + (ks * 16 + bkc) * 2));
                uint32_t r0, r1, r2, r3;
                ldmx4(r0, r1, r2, r3, bBase + off);
                b[0][bi*2  ][0] = r0; b[0][bi*2  ][1] = r1;
                b[0][bi*2+1][0] = r2; b[0][bi*2+1][1] = r3;
                ldmx4(r0, r1, r2, r3, bBase + 16384u + off);
                b[1][bi*2  ][0] = r0; b[1][bi*2  ][1] = r1;
                b[1][bi*2+1][0] = r2; b[1][bi*2+1][1] = r3;
            }
            #pragma unroll
            for (int mi = 0; mi < 4; mi++)
                #pragma unroll
                for (int ni = 0; ni < 4; ni++) {
                    mma16816(d[mi][ni], a[0][mi], b[0][ni]);  // hi*hi
                    mma16816(d[mi][ni], a[0][mi], b[1][ni]);  // hi*lo
                    mma16816(d[mi][ni], a[1][mi], b[0][ni]);  // lo*hi
                }
        }
        __syncthreads();
    }

    // epilogue
    const int g4 = lane >> 2, t4 = lane & 3;
    #pragma unroll
    for (int mi = 0; mi < 4; mi++) {
        #pragma unroll
        for (int half = 0; half < 2; half++) {
            const int m = m0 + wm * 64 + mi * 16 + g4 + half * 8;
            const int bb = m >> 11, ssq = m & (SEQ - 1);
            #pragma unroll
            for (int ni = 0; ni < 4; ni++) {
                const int n = n0 + wn * 32 + ni * 8 + t4 * 2;
                float2 v;
                v.x = d[mi][ni][half * 2 + 0];
                v.y = d[mi][ni][half * 2 + 1];
                if (SPLIT) {
                    const int h = n >> 6, dd = n & 63;
                    *(float2*)(out + (((size_t)(bb * HEADS + h)) * SEQ + ssq) * HDIM + dd) = v;
                } else {
                    *(float2*)(out + (size_t)m * EMBED + n) = v;
                }
            }
        }
    }
}

// ---------------------------------------------------------------------------
// Causal flash attention, fp32 SIMT (as in round 1; heavy tiles first).
// ---------------------------------------------------------------------------
#define PAD 68
__global__ __launch_bounds__(256) void flash_kernel(float* __restrict__ outAO)
{
    extern __shared__ float sm[];
    float* Qt = sm;
    float* Kt = sm + 64*PAD;
    float* Vs = sm + 2*64*PAD;
    float* Ps = sm + 3*64*PAD;

    const int tid = threadIdx.x;
    const int tx  = tid & 15, ty = tid >> 4;
    const int bh  = blockIdx.y;
    const int b   = bh >> 4, h = bh & 15;
    const int qt  = gridDim.x - 1 - blockIdx.x;
    const int q0  = qt * 64;

    const float* Qb = g_q + (size_t)bh * SEQ * HDIM;
    const float* Kb = g_k + (size_t)bh * SEQ * HDIM;
    const float* Vb = g_v + (size_t)bh * SEQ * HDIM;

    {
        const int r0 = tid >> 4;
        const int d0 = (tid & 15) << 2;
        #pragma unroll
        for (int it = 0; it < 4; it++) {
            int q = r0 + it * 16;
            float4 v = *(const float4*)(Qb + (size_t)(q0 + q) * HDIM + d0);
            Qt[(d0+0)*PAD + q] = v.x;
            Qt[(d0+1)*PAD + q] = v.y;
            Qt[(d0+2)*PAD + q] = v.z;
            Qt[(d0+3)*PAD + q] = v.w;
        }
    }

    float m_i[4], l_i[4], o[4][4];
    #pragma unroll
    for (int i = 0; i < 4; i++) {
        m_i[i] = -INFINITY; l_i[i] = 0.f;
        #pragma unroll
        for (int j = 0; j < 4; j++) o[i][j] = 0.f;
    }

    const float scale = 0.03125f;

    for (int kt = 0; kt <= qt; kt++) {
        const int k0 = kt * 64;
        __syncthreads();
        {
            const int r0 = tid >> 4;
            const int d0 = (tid & 15) << 2;
            #pragma unroll
            for (int it = 0; it < 4; it++) {
                int k = r0 + it * 16;
                float4 kv = *(const float4*)(Kb + (size_t)(k0 + k) * HDIM + d0);
                Kt[(d0+0)*PAD + k] = kv.x;
                Kt[(d0+1)*PAD + k] = kv.y;
                Kt[(d0+2)*PAD + k] = kv.z;
                Kt[(d0+3)*PAD + k] = kv.w;
                float4 vv = *(const float4*)(Vb + (size_t)(k0 + k) * HDIM + d0);
                *(float4*)(Vs + k*PAD + d0) = vv;
            }
        }
        __syncthreads();

        float s[4][4];
        #pragma unroll
        for (int i = 0; i < 4; i++)
            #pragma unroll
            for (int j = 0; j < 4; j++) s[i][j] = 0.f;

        #pragma unroll 8
        for (int dd = 0; dd < 64; dd++) {
            float4 qa = *(const float4*)(Qt + dd*PAD + ty*4);
            float4 ka = *(const float4*)(Kt + dd*PAD + tx*4);
            float qv[4] = {qa.x, qa.y, qa.z, qa.w};
            float kv[4] = {ka.x, ka.y, ka.z, ka.w};
            #pragma unroll
            for (int i = 0; i < 4; i++)
                #pragma unroll
                for (int j = 0; j < 4; j++)
                    s[i][j] = fmaf(qv[i], kv[j], s[i][j]);
        }

        #pragma unroll
        for (int i = 0; i < 4; i++) {
            int qg = q0 + ty*4 + i;
            #pragma unroll
            for (int j = 0; j < 4; j++) {
                int kg = k0 + tx*4 + j;
                s[i][j] = s[i][j] * scale + ((kg > qg) ? -100000.f : 0.f);
            }
        }

        #pragma unroll
        for (int i = 0; i < 4; i++) {
            float mt = fmaxf(fmaxf(s[i][0], s[i][1]), fmaxf(s[i][2], s[i][3]));
            mt = fmaxf(mt, __shfl_xor_sync(0xffffffffu, mt, 8));
            mt = fmaxf(mt, __shfl_xor_sync(0xffffffffu, mt, 4));
            mt = fmaxf(mt, __shfl_xor_sync(0xffffffffu, mt, 2));
            mt = fmaxf(mt, __shfl_xor_sync(0xffffffffu, mt, 1));
            float mnew = fmaxf(m_i[i], mt);
            float corr = __expf(m_i[i] - mnew);
            float rs = 0.f;
            #pragma unroll
            for (int j = 0; j < 4; j++) {
                s[i][j] = __expf(s[i][j] - mnew);
                rs += s[i][j];
            }
            rs += __shfl_xor_sync(0xffffffffu, rs, 8);
            rs += __shfl_xor_sync(0xffffffffu, rs, 4);
            rs += __shfl_xor_sync(0xffffffffu, rs, 2);
            rs += __shfl_xor_sync(0xffffffffu, rs, 1);
            l_i[i] = l_i[i] * corr + rs;
            m_i[i] = mnew;
            #pragma unroll
            for (int j = 0; j < 4; j++) o[i][j] *= corr;
        }

        #pragma unroll
        for (int i = 0; i < 4; i++)
            #pragma unroll
            for (int j = 0; j < 4; j++)
                Ps[(tx*4 + j)*PAD + (ty*4 + i)] = s[i][j];
        __syncthreads();

        #pragma unroll 8
        for (int k = 0; k < 64; k++) {
            float4 pa = *(const float4*)(Ps + k*PAD + ty*4);
            float4 va = *(const float4*)(Vs + k*PAD + tx*4);
            float pv[4] = {pa.x, pa.y, pa.z, pa.w};
            float vv[4] = {va.x, va.y, va.z, va.w};
            #pragma unroll
            for (int i = 0; i < 4; i++)
                #pragma unroll
                for (int j = 0; j < 4; j++)
                    o[i][j] = fmaf(pv[i], vv[j], o[i][j]);
        }
    }

    #pragma unroll
    for (int i = 0; i < 4; i++) {
        float inv = 1.f / l_i[i];
        int qg = q0 + ty*4 + i;
        float4 r;
        r.x = o[i][0] * inv; r.y = o[i][1] * inv;
        r.z = o[i][2] * inv; r.w = o[i][3] * inv;
        *(float4*)(outAO + ((size_t)(b*SEQ + qg))*EMBED + h*HDIM + tx*4) = r;
    }
}

// ---------------------------------------------------------------------------
extern "C" void kernel_launch(void* const* d_in, const int* in_sizes, int n_in,
                              void* d_out, int out_size)
{
    const float* key   = (const float*)d_in[0];
    const float* query = (const float*)d_in[1];
    const float* value = (const float*)d_in[2];
    const float* Wk    = (const float*)d_in[3];
    const float* Wq    = (const float*)d_in[4];
    const float* Wv    = (const float*)d_in[5];
    const float* Wo    = (const float*)d_in[6];
    float* out = (float*)d_out;

    float *q_, *k_, *v_, *ao_;
    __nv_bfloat16 *xh, *xl, *wh, *wl;
    cudaGetSymbolAddress((void**)&q_,  g_q);
    cudaGetSymbolAddress((void**)&k_,  g_k);
    cudaGetSymbolAddress((void**)&v_,  g_v);
    cudaGetSymbolAddress((void**)&ao_, g_ao);
    cudaGetSymbolAddress((void**)&xh,  g_xh);
    cudaGetSymbolAddress((void**)&xl,  g_xl);
    cudaGetSymbolAddress((void**)&wh,  g_wh);
    cudaGetSymbolAddress((void**)&wl,  g_wl);

    cudaFuncSetAttribute(gemm_tc<true>,  cudaFuncAttributeMaxDynamicSharedMemorySize, GSMEM);
    cudaFuncSetAttribute(gemm_tc<false>, cudaFuncAttributeMaxDynamicSharedMemorySize, GSMEM);

    const dim3 gg(M_TOT/128, EMBED/128);          // (32, 8)
    const int ACT_BLKS = (M_TOT*EMBED)/(256*4);   // 4096
    const int W_BLKS   = (EMBED*EMBED)/(256*4);   // 1024

    cvt_hilo<<<ACT_BLKS, 256>>>(query, xh, xl);
    cvt_hilo<<<W_BLKS,   256>>>(Wq,    wh, wl);
    gemm_tc<true><<<gg, 256, GSMEM>>>(xh, xl, wh, wl, q_);

    cvt_hilo<<<ACT_BLKS, 256>>>(key, xh, xl);
    cvt_hilo<<<W_BLKS,   256>>>(Wk,  wh, wl);
    gemm_tc<true><<<gg, 256, GSMEM>>>(xh, xl, wh, wl, k_);

    cvt_hilo<<<ACT_BLKS, 256>>>(value, xh, xl);
    cvt_hilo<<<W_BLKS,   256>>>(Wv,    wh, wl);
    gemm_tc<true><<<gg, 256, GSMEM>>>(xh, xl, wh, wl, v_);

    const int fsmem = 4 * 64 * PAD * (int)sizeof(float);
    cudaFuncSetAttribute(flash_kernel, cudaFuncAttributeMaxDynamicSharedMemorySize, fsmem);
    flash_kernel<<<dim3(SEQ/64, BATCH*HEADS), 256, fsmem>>>(ao_);

    cvt_hilo<<<ACT_BLKS, 256>>>(ao_, xh, xl);
    cvt_hilo<<<W_BLKS,   256>>>(Wo,  wh, wl);
    gemm_tc<false><<<gg, 256, GSMEM>>>(xh, xl, wh, wl, out);
}

// round 4
// speedup vs baseline: 3.2297x; 1.9815x over previous
#include <cuda_runtime.h>
#include <cuda_bf16.h>
#include <math.h>
#include <stdint.h>

#define EMBED 1024
#define HEADS 16
#define HDIM  64
#define BATCH 2
#define SEQ   2048
#define M_TOT (BATCH*SEQ)   // 4096

// ---------------- scratch (device globals; allocation-free) ----------------
__device__ __nv_bfloat16 g_xh[M_TOT*EMBED];
__device__ __nv_bfloat16 g_xl[M_TOT*EMBED];
__device__ __nv_bfloat16 g_wh[EMBED*EMBED];
__device__ __nv_bfloat16 g_wl[EMBED*EMBED];
__device__ __nv_bfloat16 g_qh[BATCH*HEADS*SEQ*HDIM];
__device__ __nv_bfloat16 g_ql[BATCH*HEADS*SEQ*HDIM];
__device__ __nv_bfloat16 g_kh[BATCH*HEADS*SEQ*HDIM];
__device__ __nv_bfloat16 g_kl[BATCH*HEADS*SEQ*HDIM];
__device__ __nv_bfloat16 g_vh[BATCH*HEADS*SEQ*HDIM];
__device__ __nv_bfloat16 g_vl[BATCH*HEADS*SEQ*HDIM];

// ---------------------------------------------------------------------------
// fp32 -> bf16 (hi, lo) split. 4 floats / thread.
// ---------------------------------------------------------------------------
__global__ __launch_bounds__(256) void cvt_hilo(const float* __restrict__ x,
                                                __nv_bfloat16* __restrict__ h,
                                                __nv_bfloat16* __restrict__ l)
{
    size_t i = (size_t)blockIdx.x * blockDim.x + threadIdx.x;
    float4 v = ((const float4*)x)[i];
    __nv_bfloat16 h0 = __float2bfloat16(v.x);
    __nv_bfloat16 h1 = __float2bfloat16(v.y);
    __nv_bfloat16 h2 = __float2bfloat16(v.z);
    __nv_bfloat16 h3 = __float2bfloat16(v.w);
    __nv_bfloat16 l0 = __float2bfloat16(v.x - __bfloat162float(h0));
    __nv_bfloat16 l1 = __float2bfloat16(v.y - __bfloat162float(h1));
    __nv_bfloat16 l2 = __float2bfloat16(v.z - __bfloat162float(h2));
    __nv_bfloat16 l3 = __float2bfloat16(v.w - __bfloat162float(h3));
    __nv_bfloat162* hp = (__nv_bfloat162*)h;
    __nv_bfloat162* lp = (__nv_bfloat162*)l;
    hp[2*i]   = __nv_bfloat162(h0, h1);
    hp[2*i+1] = __nv_bfloat162(h2, h3);
    lp[2*i]   = __nv_bfloat162(l0, l1);
    lp[2*i+1] = __nv_bfloat162(l2, l3);
}

// ---------------------------------------------------------------------------
// warp-MMA helpers (sm_80-class instructions; valid on plain sm_103 target)
// ---------------------------------------------------------------------------
__device__ __forceinline__ uint32_t s2u(const void* p) {
    uint32_t a;
    asm("{ .reg .u64 t; cvta.to.shared.u64 t, %1; cvt.u32.u64 %0, t; }" : "=r"(a) : "l"(p));
    return a;
}

__device__ __forceinline__ void ldmx4(uint32_t& r0, uint32_t& r1, uint32_t& r2, uint32_t& r3,
                                      uint32_t addr)
{
    asm volatile("ldmatrix.sync.aligned.m8n8.x4.shared.b16 {%0,%1,%2,%3}, [%4];"
                 : "=r"(r0), "=r"(r1), "=r"(r2), "=r"(r3) : "r"(addr));
}

__device__ __forceinline__ void ldmx4t(uint32_t& r0, uint32_t& r1, uint32_t& r2, uint32_t& r3,
                                       uint32_t addr)
{
    asm volatile("ldmatrix.sync.aligned.m8n8.x4.trans.shared.b16 {%0,%1,%2,%3}, [%4];"
                 : "=r"(r0), "=r"(r1), "=r"(r2), "=r"(r3) : "r"(addr));
}

__device__ __forceinline__ void mma16816(float* d, const uint32_t* a, const uint32_t* b)
{
    asm volatile("mma.sync.aligned.m16n8k16.row.col.f32.bf16.bf16.f32 "
                 "{%0,%1,%2,%3}, {%4,%5,%6,%7}, {%8,%9}, {%0,%1,%2,%3};"
                 : "+f"(d[0]), "+f"(d[1]), "+f"(d[2]), "+f"(d[3])
                 : "r"(a[0]), "r"(a[1]), "r"(a[2]), "r"(a[3]), "r"(b[0]), "r"(b[1]));
}

__device__ __forceinline__ void cpasync16(uint32_t saddr, const void* gaddr)
{
    asm volatile("cp.async.cg.shared.global [%0], [%1], 16;" :: "r"(saddr), "l"(gaddr));
}

__device__ __forceinline__ uint32_t swz(uint32_t off) { return off ^ ((off >> 3) & 0x70); }

__device__ __forceinline__ uint32_t pack_bf2(float x, float y) {
    __nv_bfloat162 t = __floats2bfloat162_rn(x, y);
    return reinterpret_cast<uint32_t&>(t);
}

// ---------------------------------------------------------------------------
// Tensor-core GEMM: C[m][n] = sum_k X[m][k]*W[n][k]  (fp32 via bf16 hi/lo, 3 passes)
// CTA tile 128x128, BK=64, 8 warps (2m x 4n), warptile 64x32.
// SPLIT: write hi/lo bf16 into (B,H,S,D); else fp32 (B,S,E).
// ---------------------------------------------------------------------------
#define STG_BYTES 65536
#define GSMEM     (2 * STG_BYTES)

template<bool SPLIT>
__global__ __launch_bounds__(256, 1) void gemm_tc(const __nv_bfloat16* __restrict__ xh,
                                                  const __nv_bfloat16* __restrict__ xl,
                                                  const __nv_bfloat16* __restrict__ wh,
                                                  const __nv_bfloat16* __restrict__ wl,
                                                  float* __restrict__ out,
                                                  __nv_bfloat16* __restrict__ outh,
                                                  __nv_bfloat16* __restrict__ outl)
{
    extern __shared__ char smg[];
    const uint32_t sb = s2u(smg);
    const int tid  = threadIdx.x;
    const int wid  = tid >> 5, lane = tid & 31;
    const int wm   = wid & 1;
    const int wn   = wid >> 1;
    const int m0   = blockIdx.x * 128;
    const int n0   = blockIdx.y * 128;

    const int ldr = tid >> 3;
    const int ldc = tid & 7;

    auto issue = [&](int c) {
        const int st = c & 1;
        const uint32_t sst = sb + st * STG_BYTES;
        const int kc0 = c * 64;
        const __nv_bfloat16* gAh = xh + (size_t)m0 * EMBED + kc0;
        const __nv_bfloat16* gAl = xl + (size_t)m0 * EMBED + kc0;
        const __nv_bfloat16* gBh = wh + (size_t)n0 * EMBED + kc0;
        const __nv_bfloat16* gBl = wl + (size_t)n0 * EMBED + kc0;
        #pragma unroll
        for (int it = 0; it < 4; it++) {
            const int r = ldr + it * 32;
            const uint32_t o = swz((uint32_t)(r * 128 + ldc * 16));
            const size_t g = (size_t)r * EMBED + ldc * 8;
            cpasync16(sst +          o, gAh + g);
            cpasync16(sst + 16384u + o, gAl + g);
            cpasync16(sst + 32768u + o, gBh + g);
            cpasync16(sst + 49152u + o, gBl + g);
        }
        asm volatile("cp.async.commit_group;" ::: "memory");
    };

    float d[4][4][4];
    #pragma unroll
    for (int mi = 0; mi < 4; mi++)
        #pragma unroll
        for (int ni = 0; ni < 4; ni++)
            #pragma unroll
            for (int r = 0; r < 4; r++) d[mi][ni][r] = 0.f;

    issue(0);

    const int NCHUNK = EMBED / 64;
    for (int c = 0; c < NCHUNK; c++) {
        if (c + 1 < NCHUNK) {
            issue(c + 1);
            asm volatile("cp.async.wait_group 1;" ::: "memory");
        } else {
            asm volatile("cp.async.wait_group 0;" ::: "memory");
        }
        __syncthreads();

        const uint32_t sst = sb + (c & 1) * STG_BYTES;
        const uint32_t aBase = sst;
        const uint32_t bBase = sst + 32768u;

        const int arow = lane & 15;
        const int akc  = (lane & 16) >> 1;
        const int brow = (lane & 7) | ((lane & 16) >> 1);
        const int bkc  = lane & 8;

        #pragma unroll
        for (int ks = 0; ks < 4; ks++) {
            uint32_t a[2][4][4];
            #pragma unroll
            for (int mi = 0; mi < 4; mi++) {
                const int row = wm * 64 + mi * 16 + arow;
                const uint32_t off = swz((uint32_t)(row * 128 + (ks * 16 + akc) * 2));
                ldmx4(a[0][mi][0], a[0][mi][1], a[0][mi][2], a[0][mi][3], aBase + off);
                ldmx4(a[1][mi][0], a[1][mi][1], a[1][mi][2], a[1][mi][3], aBase + 16384u + off);
            }
            uint32_t b[2][4][2];
            #pragma unroll
            for (int bi = 0; bi < 2; bi++) {
                const int row = wn * 32 + bi * 16 + brow;
                const uint32_t off = swz((uint32_t)(row * 128 + (ks * 16 + bkc) * 2));
                uint32_t r0, r1, r2, r3;
                ldmx4(r0, r1, r2, r3, bBase + off);
                b[0][bi*2  ][0] = r0; b[0][bi*2  ][1] = r1;
                b[0][bi*2+1][0] = r2; b[0][bi*2+1][1] = r3;
                ldmx4(r0, r1, r2, r3, bBase + 16384u + off);
                b[1][bi*2  ][0] = r0; b[1][bi*2  ][1] = r1;
                b[1][bi*2+1][0] = r2; b[1][bi*2+1][1] = r3;
            }
            #pragma unroll
            for (int mi = 0; mi < 4; mi++)
                #pragma unroll
                for (int ni = 0; ni < 4; ni++) {
                    mma16816(d[mi][ni], a[0][mi], b[0][ni]);
                    mma16816(d[mi][ni], a[0][mi], b[1][ni]);
                    mma16816(d[mi][ni], a[1][mi], b[0][ni]);
                }
        }
        __syncthreads();
    }

    const int g4 = lane >> 2, t4 = lane & 3;
    #pragma unroll
    for (int mi = 0; mi < 4; mi++) {
        #pragma unroll
        for (int half = 0; half < 2; half++) {
            const int m = m0 + wm * 64 + mi * 16 + g4 + half * 8;
            const int bb = m >> 11, ssq = m & (SEQ - 1);
            #pragma unroll
            for (int ni = 0; ni < 4; ni++) {
                const int n = n0 + wn * 32 + ni * 8 + t4 * 2;
                const float vx = d[mi][ni][half * 2 + 0];
                const float vy = d[mi][ni][half * 2 + 1];
                if (SPLIT) {
                    const int h = n >> 6, dd = n & 63;
                    const size_t idx = (((size_t)(bb * HEADS + h)) * SEQ + ssq) * HDIM + dd;
                    const float hx = __bfloat162float(__float2bfloat16(vx));
                    const float hy = __bfloat162float(__float2bfloat16(vy));
                    *(uint32_t*)(outh + idx) = pack_bf2(vx, vy);
                    *(uint32_t*)(outl + idx) = pack_bf2(vx - hx, vy - hy);
                } else {
                    float2 v; v.x = vx; v.y = vy;
                    *(float2*)(out + (size_t)m * EMBED + n) = v;
                }
            }
        }
    }
}

// ---------------------------------------------------------------------------
// Flash attention on HMMA (bf16 hi/lo, fp32 softmax).
// CTA: 128 q-rows x full kv sweep; 8 warps, each 16 q-rows x 128 kv per tile.
// smem: Qh/Ql 32KB + 2 stages x (Kh,Kl,Vh,Vl) 64KB = 160KB.
// ---------------------------------------------------------------------------
#define FSMEM (32768 + 2*65536)

__global__ __launch_bounds__(256, 1) void flash_tc(
    const __nv_bfloat16* __restrict__ qh, const __nv_bfloat16* __restrict__ ql,
    const __nv_bfloat16* __restrict__ kh, const __nv_bfloat16* __restrict__ kl,
    const __nv_bfloat16* __restrict__ vh, const __nv_bfloat16* __restrict__ vl,
    __nv_bfloat16* __restrict__ oh, __nv_bfloat16* __restrict__ ol)
{
    extern __shared__ char smf[];
    const uint32_t sb = s2u(smf);
    const int tid  = threadIdx.x;
    const int wid  = tid >> 5, lane = tid & 31;
    const int g4   = lane >> 2, t4 = lane & 3;
    const int bh   = blockIdx.y;
    const int b    = bh >> 4, head = bh & 15;
    const int qt   = (int)gridDim.x - 1 - (int)blockIdx.x;   // heavy tiles first
    const int q0   = qt * 128;

    const size_t bo = (size_t)bh * SEQ * HDIM;
    const __nv_bfloat16* Qhp = qh + bo + (size_t)q0 * HDIM;
    const __nv_bfloat16* Qlp = ql + bo + (size_t)q0 * HDIM;
    const __nv_bfloat16* Khp = kh + bo;
    const __nv_bfloat16* Klp = kl + bo;
    const __nv_bfloat16* Vhp = vh + bo;
    const __nv_bfloat16* Vlp = vl + bo;

    const int ldr = tid >> 3, ldc = tid & 7;
    auto loadTile = [&](uint32_t dst, const __nv_bfloat16* src) {
        #pragma unroll
        for (int it = 0; it < 4; it++) {
            const int r = ldr + it * 32;
            cpasync16(sb + dst + swz((uint32_t)(r * 128 + ldc * 16)),
                      src + (size_t)r * HDIM + ldc * 8);
        }
    };
    auto issueKV = [&](int kt) {
        const uint32_t st = 32768u + (uint32_t)(kt & 1) * 65536u;
        const size_t off = (size_t)kt * 128 * HDIM;
        loadTile(st,           Khp + off);
        loadTile(st + 16384u,  Klp + off);
        loadTile(st + 32768u,  Vhp + off);
        loadTile(st + 49152u,  Vlp + off);
        asm volatile("cp.async.commit_group;" ::: "memory");
    };

    loadTile(0u,     Qhp);
    loadTile(16384u, Qlp);
    issueKV(0);   // commit bundles Q + KV0

    float o[8][4];
    #pragma unroll
    for (int ng = 0; ng < 8; ng++)
        #pragma unroll
        for (int r = 0; r < 4; r++) o[ng][r] = 0.f;
    float m_[2] = {-INFINITY, -INFINITY};
    float l_[2] = {0.f, 0.f};

    const int arow = lane & 15;
    const int akc  = (lane & 16) >> 1;
    const int brow = (lane & 7) | ((lane & 16) >> 1);
    const int bkc  = lane & 8;
    const int vrow = lane & 15;
    const int vsel = ((lane >> 4) & 1) * 16;

    const float scale = 0.03125f;   // 1/sqrt(1024)

    for (int kt = 0; kt <= qt; kt++) {
        if (kt < qt) {
            issueKV(kt + 1);
            asm volatile("cp.async.wait_group 1;" ::: "memory");
        } else {
            asm volatile("cp.async.wait_group 0;" ::: "memory");
        }
        __syncthreads();

        const uint32_t st = sb + 32768u + (uint32_t)(kt & 1) * 65536u;

        // ---------------- S = Q K^T (hi/lo, 3 passes) ----------------
        float s[16][4];
        #pragma unroll
        for (int ni = 0; ni < 16; ni++)
            #pragma unroll
            for (int r = 0; r < 4; r++) s[ni][r] = 0.f;

        #pragma unroll
        for (int ks = 0; ks < 4; ks++) {
            uint32_t ah[4], al[4];
            const uint32_t offA = swz((uint32_t)((wid * 16 + arow) * 128 + (ks * 16 + akc) * 2));
            ldmx4(ah[0], ah[1], ah[2], ah[3], sb + offA);
            ldmx4(al[0], al[1], al[2], al[3], sb + 16384u + offA);
            #pragma unroll
            for (int bi = 0; bi < 8; bi++) {
                const uint32_t offB = swz((uint32_t)((bi * 16 + brow) * 128 + (ks * 16 + bkc) * 2));
                uint32_t h0, h1, h2, h3, l0, l1, l2, l3;
                ldmx4(h0, h1, h2, h3, st + offB);
                ldmx4(l0, l1, l2, l3, st + 16384u + offB);
                uint32_t bh0[2] = {h0, h1}, bh1[2] = {h2, h3};
                uint32_t bl0[2] = {l0, l1}, bl1[2] = {l2, l3};
                mma16816(s[bi*2],   ah, bh0);
                mma16816(s[bi*2],   ah, bl0);
                mma16816(s[bi*2],   al, bh0);
                mma16816(s[bi*2+1], ah, bh1);
                mma16816(s[bi*2+1], ah, bl1);
                mma16816(s[bi*2+1], al, bh1);
            }
        }

        // ---------------- online softmax (fp32) ----------------
        const bool diag = (kt == qt);
        const int k0 = kt * 128;
        #pragma unroll
        for (int h = 0; h < 2; h++) {
            const int qg = q0 + wid * 16 + g4 + h * 8;
            float mx = -INFINITY;
            #pragma unroll
            for (int ni = 0; ni < 16; ni++) {
                #pragma unroll
                for (int e = 0; e < 2; e++) {
                    float v = s[ni][h * 2 + e] * scale;
                    if (diag && (k0 + ni * 8 + t4 * 2 + e) > qg) v += -100000.f;
                    s[ni][h * 2 + e] = v;
                    mx = fmaxf(mx, v);
                }
            }
            mx = fmaxf(mx, __shfl_xor_sync(0xffffffffu, mx, 1));
            mx = fmaxf(mx, __shfl_xor_sync(0xffffffffu, mx, 2));
            const float mnew = fmaxf(m_[h], mx);
            const float corr = __expf(m_[h] - mnew);
            float rs = 0.f;
            #pragma unroll
            for (int ni = 0; ni < 16; ni++) {
                #pragma unroll
                for (int e = 0; e < 2; e++) {
                    const float p = __expf(s[ni][h * 2 + e] - mnew);
                    s[ni][h * 2 + e] = p;
                    rs += p;
                }
            }
            rs += __shfl_xor_sync(0xffffffffu, rs, 1);
            rs += __shfl_xor_sync(0xffffffffu, rs, 2);
            l_[h] = l_[h] * corr + rs;
            m_[h] = mnew;
            #pragma unroll
            for (int ng = 0; ng < 8; ng++) {
                o[ng][h * 2 + 0] *= corr;
                o[ng][h * 2 + 1] *= corr;
            }
        }

        // ---------------- O += P V (hi/lo, 3 passes) ----------------
        #pragma unroll
        for (int kc = 0; kc < 8; kc++) {
            // P fragments from accumulator layout (C->A identity)
            uint32_t pah[4], pal[4];
            {
                const float c00 = s[kc*2][0],   c01 = s[kc*2][1];
                const float c02 = s[kc*2][2],   c03 = s[kc*2][3];
                const float c10 = s[kc*2+1][0], c11 = s[kc*2+1][1];
                const float c12 = s[kc*2+1][2], c13 = s[kc*2+1][3];
                pah[0] = pack_bf2(c00, c01);
                pah[1] = pack_bf2(c02, c03);
                pah[2] = pack_bf2(c10, c11);
                pah[3] = pack_bf2(c12, c13);
                const float r00 = c00 - __bfloat162float(__float2bfloat16(c00));
                const float r01 = c01 - __bfloat162float(__float2bfloat16(c01));
                const float r02 = c02 - __bfloat162float(__float2bfloat16(c02));
                const float r03 = c03 - __bfloat162float(__float2bfloat16(c03));
                const float r10 = c10 - __bfloat162float(__float2bfloat16(c10));
                const float r11 = c11 - __bfloat162float(__float2bfloat16(c11));
                const float r12 = c12 - __bfloat162float(__float2bfloat16(c12));
                const float r13 = c13 - __bfloat162float(__float2bfloat16(c13));
                pal[0] = pack_bf2(r00, r01);
                pal[1] = pack_bf2(r02, r03);
                pal[2] = pack_bf2(r10, r11);
                pal[3] = pack_bf2(r12, r13);
            }
            #pragma unroll
            for (int dp = 0; dp < 4; dp++) {
                const uint32_t offV = swz((uint32_t)((kc * 16 + vrow) * 128 + dp * 32 + vsel));
                uint32_t vh0, vh1, vh2, vh3, vl0, vl1, vl2, vl3;
                ldmx4t(vh0, vh1, vh2, vh3, st + 32768u + offV);
                ldmx4t(vl0, vl1, vl2, vl3, st + 49152u + offV);
                uint32_t bvh0[2] = {vh0, vh1}, bvh1[2] = {vh2, vh3};
                uint32_t bvl0[2] = {vl0, vl1}, bvl1[2] = {vl2, vl3};
                mma16816(o[dp*2],   pah, bvh0);
                mma16816(o[dp*2],   pah, bvl0);
                mma16816(o[dp*2],   pal, bvh0);
                mma16816(o[dp*2+1], pah, bvh1);
                mma16816(o[dp*2+1], pah, bvl1);
                mma16816(o[dp*2+1], pal, bvh1);
            }
        }
        __syncthreads();   // done reading this stage before it is refilled
    }

    // ---------------- epilogue: O/l -> hi/lo bf16 (B,S,E) ----------------
    #pragma unroll
    for (int h = 0; h < 2; h++) {
        const float inv = 1.f / l_[h];
        const int qg = q0 + wid * 16 + g4 + h * 8;
        const size_t base = ((size_t)(b * SEQ + qg)) * EMBED + head * HDIM;
        #pragma unroll
        for (int ng = 0; ng < 8; ng++) {
            const float x = o[ng][h * 2 + 0] * inv;
            const float y = o[ng][h * 2 + 1] * inv;
            const float hx = __bfloat162float(__float2bfloat16(x));
            const float hy = __bfloat162float(__float2bfloat16(y));
            const size_t idx = base + ng * 8 + t4 * 2;
            *(uint32_t*)(oh + idx) = pack_bf2(x, y);
            *(uint32_t*)(ol + idx) = pack_bf2(x - hx, y - hy);
        }
    }
}

// ---------------------------------------------------------------------------
extern "C" void kernel_launch(void* const* d_in, const int* in_sizes, int n_in,
                              void* d_out, int out_size)
{
    const float* key   = (const float*)d_in[0];
    const float* query = (const float*)d_in[1];
    const float* value = (const float*)d_in[2];
    const float* Wk    = (const float*)d_in[3];
    const float* Wq    = (const float*)d_in[4];
    const float* Wv    = (const float*)d_in[5];
    const float* Wo    = (const float*)d_in[6];
    float* out = (float*)d_out;

    __nv_bfloat16 *xh, *xl, *wh, *wl;
    __nv_bfloat16 *qh_, *ql_, *kh_, *kl_, *vh_, *vl_;
    cudaGetSymbolAddress((void**)&xh,  g_xh);
    cudaGetSymbolAddress((void**)&xl,  g_xl);
    cudaGetSymbolAddress((void**)&wh,  g_wh);
    cudaGetSymbolAddress((void**)&wl,  g_wl);
    cudaGetSymbolAddress((void**)&qh_, g_qh);
    cudaGetSymbolAddress((void**)&ql_, g_ql);
    cudaGetSymbolAddress((void**)&kh_, g_kh);
    cudaGetSymbolAddress((void**)&kl_, g_kl);
    cudaGetSymbolAddress((void**)&vh_, g_vh);
    cudaGetSymbolAddress((void**)&vl_, g_vl);

    cudaFuncSetAttribute(gemm_tc<true>,  cudaFuncAttributeMaxDynamicSharedMemorySize, GSMEM);
    cudaFuncSetAttribute(gemm_tc<false>, cudaFuncAttributeMaxDynamicSharedMemorySize, GSMEM);
    cudaFuncSetAttribute(flash_tc,       cudaFuncAttributeMaxDynamicSharedMemorySize, FSMEM);

    const dim3 gg(M_TOT/128, EMBED/128);          // (32, 8)
    const int ACT_BLKS = (M_TOT*EMBED)/(256*4);   // 4096
    const int W_BLKS   = (EMBED*EMBED)/(256*4);   // 1024

    cvt_hilo<<<ACT_BLKS, 256>>>(query, xh, xl);
    cvt_hilo<<<W_BLKS,   256>>>(Wq,    wh, wl);
    gemm_tc<true><<<gg, 256, GSMEM>>>(xh, xl, wh, wl, nullptr, qh_, ql_);

    cvt_hilo<<<ACT_BLKS, 256>>>(key, xh, xl);
    cvt_hilo<<<W_BLKS,   256>>>(Wk,  wh, wl);
    gemm_tc<true><<<gg, 256, GSMEM>>>(xh, xl, wh, wl, nullptr, kh_, kl_);

    cvt_hilo<<<ACT_BLKS, 256>>>(value, xh, xl);
    cvt_hilo<<<W_BLKS,   256>>>(Wv,    wh, wl);
    gemm_tc<true><<<gg, 256, GSMEM>>>(xh, xl, wh, wl, nullptr, vh_, vl_);

    // flash writes its hi/lo output straight into xh/xl (input of final GEMM)
    flash_tc<<<dim3(SEQ/128, BATCH*HEADS), 256, FSMEM>>>(qh_, ql_, kh_, kl_, vh_, vl_, xh, xl);

    cvt_hilo<<<W_BLKS, 256>>>(Wo, wh, wl);
    gemm_tc<false><<<gg, 256, GSMEM>>>(xh, xl, wh, wl, out, nullptr, nullptr);
}

// round 5
// speedup vs baseline: 6.9502x; 2.1519x over previous
#include <cuda_runtime.h>
#include <cuda_fp16.h>
#include <math.h>
#include <stdint.h>

#define EMBED 1024
#define HEADS 16
#define HDIM  64
#define BATCH 2
#define SEQ   2048
#define M_TOT (BATCH*SEQ)   // 4096

// ---------------- scratch (device globals; allocation-free) ----------------
__device__ __align__(16) __half g_x16[M_TOT*EMBED];
__device__ __align__(16) __half g_w16[EMBED*EMBED];
__device__ __align__(16) __half g_q16[BATCH*HEADS*SEQ*HDIM];
__device__ __align__(16) __half g_k16[BATCH*HEADS*SEQ*HDIM];
__device__ __align__(16) __half g_v16[BATCH*HEADS*SEQ*HDIM];

// ---------------------------------------------------------------------------
// fp32 -> fp16 conversion. 4 floats / thread.
// ---------------------------------------------------------------------------
__global__ __launch_bounds__(256) void cvt_h(const float* __restrict__ x,
                                             __half* __restrict__ h)
{
    size_t i = (size_t)blockIdx.x * blockDim.x + threadIdx.x;
    float4 v = ((const float4*)x)[i];
    __half2 a = __floats2half2_rn(v.x, v.y);
    __half2 b = __floats2half2_rn(v.z, v.w);
    uint2 r;
    r.x = reinterpret_cast<uint32_t&>(a);
    r.y = reinterpret_cast<uint32_t&>(b);
    ((uint2*)h)[i] = r;
}

// ---------------------------------------------------------------------------
// warp-MMA helpers
// ---------------------------------------------------------------------------
__device__ __forceinline__ uint32_t s2u(const void* p) {
    uint32_t a;
    asm("{ .reg .u64 t; cvta.to.shared.u64 t, %1; cvt.u32.u64 %0, t; }" : "=r"(a) : "l"(p));
    return a;
}

__device__ __forceinline__ void ldmx4(uint32_t& r0, uint32_t& r1, uint32_t& r2, uint32_t& r3,
                                      uint32_t addr)
{
    asm volatile("ldmatrix.sync.aligned.m8n8.x4.shared.b16 {%0,%1,%2,%3}, [%4];"
                 : "=r"(r0), "=r"(r1), "=r"(r2), "=r"(r3) : "r"(addr));
}

__device__ __forceinline__ void ldmx4t(uint32_t& r0, uint32_t& r1, uint32_t& r2, uint32_t& r3,
                                       uint32_t addr)
{
    asm volatile("ldmatrix.sync.aligned.m8n8.x4.trans.shared.b16 {%0,%1,%2,%3}, [%4];"
                 : "=r"(r0), "=r"(r1), "=r"(r2), "=r"(r3) : "r"(addr));
}

__device__ __forceinline__ void mma16816(float* d, const uint32_t* a, const uint32_t* b)
{
    asm volatile("mma.sync.aligned.m16n8k16.row.col.f32.f16.f16.f32 "
                 "{%0,%1,%2,%3}, {%4,%5,%6,%7}, {%8,%9}, {%0,%1,%2,%3};"
                 : "+f"(d[0]), "+f"(d[1]), "+f"(d[2]), "+f"(d[3])
                 : "r"(a[0]), "r"(a[1]), "r"(a[2]), "r"(a[3]), "r"(b[0]), "r"(b[1]));
}

__device__ __forceinline__ void cpasync16(uint32_t saddr, const void* gaddr)
{
    asm volatile("cp.async.cg.shared.global [%0], [%1], 16;" :: "r"(saddr), "l"(gaddr));
}

__device__ __forceinline__ uint32_t swz(uint32_t off) { return off ^ ((off >> 3) & 0x70); }

__device__ __forceinline__ uint32_t pack_h2(float x, float y) {
    __half2 t = __floats2half2_rn(x, y);
    return reinterpret_cast<uint32_t&>(t);
}

// ---------------------------------------------------------------------------
// Tensor-core GEMM: C[m][n] = sum_k X[m][k]*W[n][k]  (fp16 single pass)
// CTA tile 128x128, BK=64, 8 warps (2m x 4n), 4-stage cp.async pipeline.
// SPLIT: write fp16 into (B,H,S,D); else fp32 (B,S,E).
// ---------------------------------------------------------------------------
#define GSTG  32768u                   // A 16K | B 16K
#define GSMEM (4 * GSTG)               // 128 KB

template<bool SPLIT>
__global__ __launch_bounds__(256, 1) void gemm_tc(const __half* __restrict__ x16,
                                                  const __half* __restrict__ w16,
                                                  float* __restrict__ out,
                                                  __half* __restrict__ outh)
{
    extern __shared__ char smg[];
    const uint32_t sb = s2u(smg);
    const int tid  = threadIdx.x;
    const int wid  = tid >> 5, lane = tid & 31;
    const int wm   = wid & 1;
    const int wn   = wid >> 1;
    const int m0   = blockIdx.x * 128;
    const int n0   = blockIdx.y * 128;

    const int ldr = tid >> 3;          // 0..31
    const int ldc = tid & 7;           // 0..7

    auto issue = [&](int c, bool real) {
        if (real) {
            const uint32_t sst = sb + (uint32_t)(c & 3) * GSTG;
            const int kc0 = c * 64;
            const __half* gA = x16 + (size_t)m0 * EMBED + kc0;
            const __half* gB = w16 + (size_t)n0 * EMBED + kc0;
            #pragma unroll
            for (int it = 0; it < 4; it++) {
                const int r = ldr + it * 32;
                const uint32_t o = swz((uint32_t)(r * 128 + ldc * 16));
                const size_t g = (size_t)r * EMBED + ldc * 8;
                cpasync16(sst +          o, gA + g);
                cpasync16(sst + 16384u + o, gB + g);
            }
        }
        asm volatile("cp.async.commit_group;" ::: "memory");
    };

    float d[4][4][4];
    #pragma unroll
    for (int mi = 0; mi < 4; mi++)
        #pragma unroll
        for (int ni = 0; ni < 4; ni++)
            #pragma unroll
            for (int r = 0; r < 4; r++) d[mi][ni][r] = 0.f;

    issue(0, true); issue(1, true); issue(2, true); issue(3, true);

    const int arow = lane & 15;
    const int akc  = (lane & 16) >> 1;
    const int brow = (lane & 7) | ((lane & 16) >> 1);
    const int bkc  = lane & 8;

    const int NCHUNK = EMBED / 64;   // 16
    for (int c = 0; c < NCHUNK; c++) {
        asm volatile("cp.async.wait_group 3;" ::: "memory");
        __syncthreads();

        const uint32_t sst = sb + (uint32_t)(c & 3) * GSTG;
        const uint32_t bBase = sst + 16384u;

        #pragma unroll
        for (int ks = 0; ks < 4; ks++) {
            uint32_t a[4][4];
            #pragma unroll
            for (int mi = 0; mi < 4; mi++) {
                const int row = wm * 64 + mi * 16 + arow;
                const uint32_t off = swz((uint32_t)(row * 128 + (ks * 16 + akc) * 2));
                ldmx4(a[mi][0], a[mi][1], a[mi][2], a[mi][3], sst + off);
            }
            uint32_t b[4][2];
            #pragma unroll
            for (int bi = 0; bi < 2; bi++) {
                const int row = wn * 32 + bi * 16 + brow;
                const uint32_t off = swz((uint32_t)(row * 128 + (ks * 16 + bkc) * 2));
                uint32_t r0, r1, r2, r3;
                ldmx4(r0, r1, r2, r3, bBase + off);
                b[bi*2  ][0] = r0; b[bi*2  ][1] = r1;
                b[bi*2+1][0] = r2; b[bi*2+1][1] = r3;
            }
            #pragma unroll
            for (int mi = 0; mi < 4; mi++)
                #pragma unroll
                for (int ni = 0; ni < 4; ni++)
                    mma16816(d[mi][ni], a[mi], b[ni]);
        }
        __syncthreads();
        issue(c + 4, c + 4 < NCHUNK);
    }

    const int g4 = lane >> 2, t4 = lane & 3;
    #pragma unroll
    for (int mi = 0; mi < 4; mi++) {
        #pragma unroll
        for (int half = 0; half < 2; half++) {
            const int m = m0 + wm * 64 + mi * 16 + g4 + half * 8;
            const int bb = m >> 11, ssq = m & (SEQ - 1);
            #pragma unroll
            for (int ni = 0; ni < 4; ni++) {
                const int n = n0 + wn * 32 + ni * 8 + t4 * 2;
                const float vx = d[mi][ni][half * 2 + 0];
                const float vy = d[mi][ni][half * 2 + 1];
                if (SPLIT) {
                    const int h = n >> 6, dd = n & 63;
                    const size_t idx = (((size_t)(bb * HEADS + h)) * SEQ + ssq) * HDIM + dd;
                    *(uint32_t*)(outh + idx) = pack_h2(vx, vy);
                } else {
                    float2 v; v.x = vx; v.y = vy;
                    *(float2*)(out + (size_t)m * EMBED + n) = v;
                }
            }
        }
    }
}

// ---------------------------------------------------------------------------
// Flash attention on HMMA (fp16 single pass, fp32 softmax).
// CTA: 128 q-rows; 8 warps, each 16 q-rows x 128 kv per tile.
// smem: Q 16KB + 4 stages x (K 16KB + V 16KB) = 144KB.
// ---------------------------------------------------------------------------
#define FSTG  32768u
#define FSMEM (16384 + 4 * FSTG)

__global__ __launch_bounds__(256, 1) void flash_tc(
    const __half* __restrict__ q16, const __half* __restrict__ k16,
    const __half* __restrict__ v16, __half* __restrict__ oh)
{
    extern __shared__ char smf[];
    const uint32_t sb = s2u(smf);
    const int tid  = threadIdx.x;
    const int wid  = tid >> 5, lane = tid & 31;
    const int g4   = lane >> 2, t4 = lane & 3;
    const int bh   = blockIdx.y;
    const int b    = bh >> 4, head = bh & 15;
    const int qt   = (int)gridDim.x - 1 - (int)blockIdx.x;   // heavy tiles first
    const int q0   = qt * 128;

    const size_t bo = (size_t)bh * SEQ * HDIM;
    const __half* Qp = q16 + bo + (size_t)q0 * HDIM;
    const __half* Kp = k16 + bo;
    const __half* Vp = v16 + bo;

    const int ldr = tid >> 3, ldc = tid & 7;
    auto loadTile = [&](uint32_t dst, const __half* src) {
        #pragma unroll
        for (int it = 0; it < 4; it++) {
            const int r = ldr + it * 32;
            cpasync16(sb + dst + swz((uint32_t)(r * 128 + ldc * 16)),
                      src + (size_t)r * HDIM + ldc * 8);
        }
    };
    auto issueKV = [&](int kt, bool real) {
        if (real) {
            const uint32_t st = 16384u + (uint32_t)(kt & 3) * FSTG;
            const size_t off = (size_t)kt * 128 * HDIM;
            loadTile(st,           Kp + off);
            loadTile(st + 16384u,  Vp + off);
        }
        asm volatile("cp.async.commit_group;" ::: "memory");
    };

    loadTile(0u, Qp);               // joins group 0
    issueKV(0, true);
    issueKV(1, 1 <= qt);
    issueKV(2, 2 <= qt);
    issueKV(3, 3 <= qt);

    float o[8][4];
    #pragma unroll
    for (int ng = 0; ng < 8; ng++)
        #pragma unroll
        for (int r = 0; r < 4; r++) o[ng][r] = 0.f;
    float m_[2] = {-INFINITY, -INFINITY};
    float l_[2] = {0.f, 0.f};

    const int arow = lane & 15;
    const int akc  = (lane & 16) >> 1;
    const int brow = (lane & 7) | ((lane & 16) >> 1);
    const int bkc  = lane & 8;
    const int vrow = lane & 15;
    const int vsel = ((lane >> 4) & 1) * 16;

    const float scale = 0.03125f;   // 1/sqrt(1024)

    for (int kt = 0; kt <= qt; kt++) {
        asm volatile("cp.async.wait_group 3;" ::: "memory");
        __syncthreads();

        const uint32_t st = sb + 16384u + (uint32_t)(kt & 3) * FSTG;

        // ---------------- S = Q K^T ----------------
        float s[16][4];
        #pragma unroll
        for (int ni = 0; ni < 16; ni++)
            #pragma unroll
            for (int r = 0; r < 4; r++) s[ni][r] = 0.f;

        #pragma unroll
        for (int ks = 0; ks < 4; ks++) {
            uint32_t a[4];
            const uint32_t offA = swz((uint32_t)((wid * 16 + arow) * 128 + (ks * 16 + akc) * 2));
            ldmx4(a[0], a[1], a[2], a[3], sb + offA);
            #pragma unroll
            for (int bi = 0; bi < 8; bi++) {
                const uint32_t offB = swz((uint32_t)((bi * 16 + brow) * 128 + (ks * 16 + bkc) * 2));
                uint32_t r0, r1, r2, r3;
                ldmx4(r0, r1, r2, r3, st + offB);
                uint32_t b0[2] = {r0, r1}, b1[2] = {r2, r3};
                mma16816(s[bi*2],   a, b0);
                mma16816(s[bi*2+1], a, b1);
            }
        }

        // ---------------- online softmax (fp32) ----------------
        const bool diag = (kt == qt);
        const int k0 = kt * 128;
        #pragma unroll
        for (int h = 0; h < 2; h++) {
            const int qg = q0 + wid * 16 + g4 + h * 8;
            float mx = -INFINITY;
            #pragma unroll
            for (int ni = 0; ni < 16; ni++) {
                #pragma unroll
                for (int e = 0; e < 2; e++) {
                    float v = s[ni][h * 2 + e] * scale;
                    if (diag && (k0 + ni * 8 + t4 * 2 + e) > qg) v += -100000.f;
                    s[ni][h * 2 + e] = v;
                    mx = fmaxf(mx, v);
                }
            }
            mx = fmaxf(mx, __shfl_xor_sync(0xffffffffu, mx, 1));
            mx = fmaxf(mx, __shfl_xor_sync(0xffffffffu, mx, 2));
            const float mnew = fmaxf(m_[h], mx);
            const float corr = __expf(m_[h] - mnew);
            float rs = 0.f;
            #pragma unroll
            for (int ni = 0; ni < 16; ni++) {
                #pragma unroll
                for (int e = 0; e < 2; e++) {
                    const float p = __expf(s[ni][h * 2 + e] - mnew);
                    s[ni][h * 2 + e] = p;
                    rs += p;
                }
            }
            rs += __shfl_xor_sync(0xffffffffu, rs, 1);
            rs += __shfl_xor_sync(0xffffffffu, rs, 2);
            l_[h] = l_[h] * corr + rs;
            m_[h] = mnew;
            #pragma unroll
            for (int ng = 0; ng < 8; ng++) {
                o[ng][h * 2 + 0] *= corr;
                o[ng][h * 2 + 1] *= corr;
            }
        }

        // ---------------- O += P V ----------------
        #pragma unroll
        for (int kc = 0; kc < 8; kc++) {
            uint32_t pa[4];
            pa[0] = pack_h2(s[kc*2][0],   s[kc*2][1]);
            pa[1] = pack_h2(s[kc*2][2],   s[kc*2][3]);
            pa[2] = pack_h2(s[kc*2+1][0], s[kc*2+1][1]);
            pa[3] = pack_h2(s[kc*2+1][2], s[kc*2+1][3]);
            #pragma unroll
            for (int dp = 0; dp < 4; dp++) {
                const uint32_t offV = swz((uint32_t)((kc * 16 + vrow) * 128 + dp * 32 + vsel));
                uint32_t v0, v1, v2, v3;
                ldmx4t(v0, v1, v2, v3, st + 16384u + offV);
                uint32_t bv0[2] = {v0, v1}, bv1[2] = {v2, v3};
                mma16816(o[dp*2],   pa, bv0);
                mma16816(o[dp*2+1], pa, bv1);
            }
        }
        __syncthreads();
        issueKV(kt + 4, kt + 4 <= qt);
    }

    // ---------------- epilogue: O/l -> fp16 (B,S,E) ----------------
    #pragma unroll
    for (int h = 0; h < 2; h++) {
        const float inv = 1.f / l_[h];
        const int qg = q0 + wid * 16 + g4 + h * 8;
        const size_t base = ((size_t)(b * SEQ + qg)) * EMBED + head * HDIM;
        #pragma unroll
        for (int ng = 0; ng < 8; ng++) {
            const float x = o[ng][h * 2 + 0] * inv;
            const float y = o[ng][h * 2 + 1] * inv;
            *(uint32_t*)(oh + base + ng * 8 + t4 * 2) = pack_h2(x, y);
        }
    }
}

// ---------------------------------------------------------------------------
extern "C" void kernel_launch(void* const* d_in, const int* in_sizes, int n_in,
                              void* d_out, int out_size)
{
    const float* key   = (const float*)d_in[0];
    const float* query = (const float*)d_in[1];
    const float* value = (const float*)d_in[2];
    const float* Wk    = (const float*)d_in[3];
    const float* Wq    = (const float*)d_in[4];
    const float* Wv    = (const float*)d_in[5];
    const float* Wo    = (const float*)d_in[6];
    float* out = (float*)d_out;

    __half *x16, *w16, *q16, *k16, *v16;
    cudaGetSymbolAddress((void**)&x16, g_x16);
    cudaGetSymbolAddress((void**)&w16, g_w16);
    cudaGetSymbolAddress((void**)&q16, g_q16);
    cudaGetSymbolAddress((void**)&k16, g_k16);
    cudaGetSymbolAddress((void**)&v16, g_v16);

    cudaFuncSetAttribute(gemm_tc<true>,  cudaFuncAttributeMaxDynamicSharedMemorySize, GSMEM);
    cudaFuncSetAttribute(gemm_tc<false>, cudaFuncAttributeMaxDynamicSharedMemorySize, GSMEM);
    cudaFuncSetAttribute(flash_tc,       cudaFuncAttributeMaxDynamicSharedMemorySize, FSMEM);

    const dim3 gg(M_TOT/128, EMBED/128);          // (32, 8)
    const int ACT_BLKS = (M_TOT*EMBED)/(256*4);   // 4096
    const int W_BLKS   = (EMBED*EMBED)/(256*4);   // 1024

    cvt_h<<<ACT_BLKS, 256>>>(query, x16);
    cvt_h<<<W_BLKS,   256>>>(Wq,    w16);
    gemm_tc<true><<<gg, 256, GSMEM>>>(x16, w16, nullptr, q16);

    cvt_h<<<ACT_BLKS, 256>>>(key, x16);
    cvt_h<<<W_BLKS,   256>>>(Wk,  w16);
    gemm_tc<true><<<gg, 256, GSMEM>>>(x16, w16, nullptr, k16);

    cvt_h<<<ACT_BLKS, 256>>>(value, x16);
    cvt_h<<<W_BLKS,   256>>>(Wv,    w16);
    gemm_tc<true><<<gg, 256, GSMEM>>>(x16, w16, nullptr, v16);

    // flash writes fp16 AO straight into x16 (input of final GEMM)
    flash_tc<<<dim3(SEQ/128, BATCH*HEADS), 256, FSMEM>>>(q16, k16, v16, x16);

    cvt_h<<<W_BLKS, 256>>>(Wo, w16);
    gemm_tc<false><<<gg, 256, GSMEM>>>(x16, w16, out, nullptr);
}